// round 12
// baseline (speedup 1.0000x reference)
#include <cuda_runtime.h>
#include <cuda_fp16.h>
#include <stdint.h>

// ============================================================================
// Llama4TextExperts grouped GEMM + SwiGLU, fp32 in/out.
// Single-term fp16 HMMA (mma.m16n8k16.f32.f16), fp32 accumulate.
// Persistent warp-specialized: 16 consumer warps @32x32 (4m x 4n) + 4 producer
// warps, 4-stage 32KB smem ring.
//   GEMM1: X(8,1024,2048) @ Wgu -> SwiGLU -> g_scr (fp16, 64MB)
//   GEMM2: g_scr @ Wd -> out (8192,2048) fp32
// ============================================================================

#define STAGE_BYTES 32768
#define NSTAGE 4
#define SMEM_BYTES (1024 + NSTAGE * STAGE_BYTES)
#define NSM 148

static __device__ __half g_scr[(size_t)8 * 1024 * 4096];   // 64 MB fp16 inter

// ---------------- helpers ----------------
__device__ __forceinline__ uint32_t s2u(const void* p) {
    uint32_t a;
    asm("{ .reg .u64 t; cvta.to.shared.u64 t, %1; cvt.u32.u64 %0, t; }" : "=r"(a) : "l"(p));
    return a;
}
__device__ __forceinline__ uint32_t swzA(uint32_t o) { return o ^ ((o >> 3) & 0x70); }  // 128B rows
__device__ __forceinline__ uint32_t swzB(uint32_t o) { return o ^ ((o >> 4) & 0x70); }  // 256B rows

__device__ __forceinline__ uint32_t pkh(float a, float b) {
    __half2 h = __floats2half2_rn(a, b);   // .x=a in low 16 bits
    return *reinterpret_cast<uint32_t*>(&h);
}
__device__ __forceinline__ float silu_mul(float g, float u) {
    return u * __fdividef(g, 1.0f + __expf(-g));
}

__device__ __forceinline__ void ldsm4(uint32_t* r, uint32_t addr) {
    asm volatile("ldmatrix.sync.aligned.m8n8.x4.shared.b16 {%0,%1,%2,%3}, [%4];"
                 : "=r"(r[0]), "=r"(r[1]), "=r"(r[2]), "=r"(r[3]) : "r"(addr));
}
__device__ __forceinline__ void ldsm4t(uint32_t* r, uint32_t addr) {
    asm volatile("ldmatrix.sync.aligned.m8n8.x4.trans.shared.b16 {%0,%1,%2,%3}, [%4];"
                 : "=r"(r[0]), "=r"(r[1]), "=r"(r[2]), "=r"(r[3]) : "r"(addr));
}
__device__ __forceinline__ void mma16816(float* c, const uint32_t* a, const uint32_t* b) {
    asm volatile(
        "mma.sync.aligned.m16n8k16.row.col.f32.f16.f16.f32 "
        "{%0,%1,%2,%3}, {%4,%5,%6,%7}, {%8,%9}, {%0,%1,%2,%3};"
        : "+f"(c[0]), "+f"(c[1]), "+f"(c[2]), "+f"(c[3])
        : "r"(a[0]), "r"(a[1]), "r"(a[2]), "r"(a[3]), "r"(b[0]), "r"(b[1]));
}

#define MBAR_INIT(addr, cnt) \
    asm volatile("mbarrier.init.shared.b64 [%0], %1;" :: "r"(addr), "r"((uint32_t)(cnt)) : "memory")
#define MBAR_ARRIVE(addr) \
    asm volatile("mbarrier.arrive.shared.b64 _, [%0];" :: "r"(addr) : "memory")
#define MBAR_WAIT(mbar_addr, phase_parity) do {                                            \
    uint32_t _mbar = (uint32_t)(mbar_addr);                                                \
    uint32_t _par  = (uint32_t)(phase_parity);                                             \
    uint32_t _done;                                                                        \
    asm volatile(                                                                          \
        "{\n\t.reg .pred p;\n\t"                                                           \
        "mbarrier.try_wait.parity.acquire.cta.shared::cta.b64 p, [%1], %2;\n\t"            \
        "selp.b32 %0, 1, 0, p;\n\t}"                                                       \
        : "=r"(_done) : "r"(_mbar), "r"(_par) : "memory");                                 \
    if (!_done) {                                                                          \
        asm volatile(                                                                      \
            "{\n\t.reg .pred P1;\n\t"                                                      \
            "WL_%=:\n\t"                                                                   \
            "mbarrier.try_wait.parity.acquire.cta.shared::cta.b64 P1, [%0], %1, 0x989680;\n\t" \
            "@P1 bra.uni WD_%=;\n\t"                                                       \
            "bra.uni WL_%=;\n\t"                                                           \
            "WD_%=:\n\t}"                                                                  \
            :: "r"(_mbar), "r"(_par) : "memory");                                          \
    }                                                                                      \
} while (0)

// ============================================================================
//   KDIM : reduction dim (2048 / 4096),  NTILE: n-tiles per expert (64 / 16)
//   MODE2=false: GEMM1. A = X fp32 (w2048) -> fp16. B = Wgu (w8192), warp-
//                paired gate/up at 16-col granularity: tile col n' ->
//                g=n'>>5, pair=n'&15, kind=(n'>>4)&1;
//                global col = nt*64 + g*16 + pair + kind*4096.
//                Epilogue: register SwiGLU -> g_scr fp16.
//   MODE2=true : GEMM2. A = g_scr fp16 (w4096, raw copy); B = Wd; C fp32.
// Stage (32KB): Ah@0 (128 rows x 128B, swzA), Bh@16K (64 k-rows x 256B, swzB).
// Consumers: 16 warps, 4(m) x 4(n), 32x32 tiles. Producers: 4 warps.
// ============================================================================
template <int KDIM, int NTILE, bool MODE2>
__global__ __launch_bounds__(640, 1) void gemm_ker(const float* __restrict__ A_,
                                                   const float* __restrict__ B_,
                                                   float* __restrict__ C_) {
    extern __shared__ char smem[];
    constexpr int NC   = KDIM / 64;
    constexpr int NWB  = MODE2 ? 2048 : 8192;   // B row width
    constexpr int PERE = 8 * NTILE;             // tiles per expert
    constexpr int TOT  = 8 * PERE;              // total tiles

    const int tid  = threadIdx.x;
    const int wid  = tid >> 5;
    const int lane = tid & 31;

    const uint32_t smbase  = s2u(smem);
    const uint32_t tiles_u = (smbase + 1023) & ~1023u;
    char* tiles = smem + (tiles_u - smbase);
    const uint32_t full0  = smbase;        // full[s]  @ +8s, count=128
    const uint32_t empty0 = smbase + 32;   // empty[s] @ +8s, count=16

    if (tid == 0) {
        #pragma unroll
        for (int s = 0; s < NSTAGE; s++) {
            MBAR_INIT(full0 + 8 * s, 128);
            MBAR_INIT(empty0 + 8 * s, 16);
        }
    }
    __syncthreads();

    if (tid >= 512) {
        // ===================== PRODUCERS (warps 16..19) =====================
        const int pt   = tid - 512;          // 0..127
        const int a_c4 = pt & 15;            // 8B unit within 128B A row
        const int a_r0 = pt >> 4;            // 0..7
        const int b_n4 = pt & 31;            // 4-col unit in 128-n B row
        const int b_k0 = pt >> 5;            // 0..3

        int s = 0, u = 0;
        for (int t = blockIdx.x; t < TOT; t += gridDim.x) {
            const int e   = t / PERE;
            const int r   = t % PERE;
            const int sup = r >> 6;
            const int r2  = r & 63;
            const int mt  = r2 & 7;
            const int nt  = sup * 8 + (r2 >> 3);

            const float*  Apf = nullptr;
            const __half* Aph = nullptr;
            if (MODE2) Aph = g_scr + (size_t)(e * 1024 + mt * 128) * 4096 + a_c4 * 4;
            else       Apf = A_ + (size_t)(e * 1024 + mt * 128) * 2048 + a_c4 * 4;

            size_t bcol;
            if (MODE2) {
                bcol = (size_t)nt * 128 + b_n4 * 4;
            } else {
                const int np   = b_n4 * 4;
                const int g    = np >> 5;
                const int pair = np & 15;
                const int kind = (np >> 4) & 1;
                bcol = (size_t)nt * 64 + g * 16 + pair + (size_t)kind * 4096;
            }
            const float* Bp = B_ + (size_t)e * KDIM * NWB + bcol;

            for (int c = 0; c < NC; c++) {
                MBAR_WAIT(empty0 + 8 * s, u ^ 1);
                char* stg = tiles + s * STAGE_BYTES;
                const int kb = c * 64;

                // ---- A tile: 128 rows x 64 k fp16 ----
                #pragma unroll
                for (int p = 0; p < 16; p++) {
                    const int row = a_r0 + p * 8;
                    const uint32_t off = swzA((uint32_t)(row * 128 + a_c4 * 8));
                    if (MODE2) {
                        *reinterpret_cast<uint2*>(stg + off) =
                            *reinterpret_cast<const uint2*>(Aph + (size_t)row * 4096 + kb);
                    } else {
                        float4 v = *reinterpret_cast<const float4*>(Apf + (size_t)row * 2048 + kb);
                        *reinterpret_cast<uint2*>(stg + off) =
                            make_uint2(pkh(v.x, v.y), pkh(v.z, v.w));
                    }
                }
                // ---- B tile: 64 k-rows x 128 n fp16 ----
                #pragma unroll
                for (int p = 0; p < 16; p++) {
                    const int k = b_k0 + p * 4;
                    float4 v = *reinterpret_cast<const float4*>(Bp + (size_t)(kb + k) * NWB);
                    const uint32_t off = swzB((uint32_t)(k * 256 + b_n4 * 8));
                    *reinterpret_cast<uint2*>(stg + 16384 + off) =
                        make_uint2(pkh(v.x, v.y), pkh(v.z, v.w));
                }
                MBAR_ARRIVE(full0 + 8 * s);
                if (++s == NSTAGE) { s = 0; u ^= 1; }
            }
        }
        return;
    }

    // ======================= CONSUMERS (warps 0..15) =======================
    // 4(m) x 4(n) warp grid, 32x32 tiles: wm = wid>>2 (0..3), wn = wid&3.
    const int wm = wid >> 2;
    const int wn = wid & 3;

    const int lane15 = lane & 15;
    const int seg    = (lane >> 4) * 16;
    const uint32_t lxor = (uint32_t)((lane & 7) << 4);
    uint32_t a_row[2], b_colx[2];
    #pragma unroll
    for (int st = 0; st < 2; st++)
        a_row[st] = (uint32_t)((wm * 32 + st * 16 + lane15) * 128);
    #pragma unroll
    for (int ng = 0; ng < 2; ng++)
        b_colx[ng] = (uint32_t)(((wn * 32 + ng * 16) * 2 + seg)) ^ lxor;
    const uint32_t b_rowb = (uint32_t)(lane15 * 256);

    int s = 0, u = 0;
    for (int t = blockIdx.x; t < TOT; t += gridDim.x) {
        const int e   = t / PERE;
        const int r   = t % PERE;
        const int sup = r >> 6;
        const int r2  = r & 63;
        const int mt  = r2 & 7;
        const int nt  = sup * 8 + (r2 >> 3);

        float acc[2][4][4];
        #pragma unroll
        for (int st = 0; st < 2; st++)
            #pragma unroll
            for (int j = 0; j < 4; j++)
                #pragma unroll
                for (int i = 0; i < 4; i++) acc[st][j][i] = 0.0f;

        for (int c = 0; c < NC; c++) {
            MBAR_WAIT(full0 + 8 * s, u);
            const uint32_t AhU = tiles_u + s * STAGE_BYTES;
            const uint32_t BhU = AhU + 16384;

            #pragma unroll
            for (int ks = 0; ks < 4; ks++) {
                const uint32_t acol = (uint32_t)(ks * 32 + seg) ^ lxor;
                const uint32_t brow = b_rowb + (uint32_t)(ks * 4096);
                uint32_t ah[2][4], bh[2][4];
                #pragma unroll
                for (int st = 0; st < 2; st++)
                    ldsm4(ah[st], AhU + a_row[st] + acol);
                #pragma unroll
                for (int ng = 0; ng < 2; ng++)
                    ldsm4t(bh[ng], BhU + brow + b_colx[ng]);
                #pragma unroll
                for (int st = 0; st < 2; st++)
                    #pragma unroll
                    for (int ng = 0; ng < 2; ng++)
                        #pragma unroll
                        for (int hf = 0; hf < 2; hf++)
                            mma16816(acc[st][ng * 2 + hf], ah[st], &bh[ng][2 * hf]);
            }
            if (lane == 0) MBAR_ARRIVE(empty0 + 8 * s);
            if (++s == NSTAGE) { s = 0; u ^= 1; }
        }

        // ----------------- epilogue (register-only, overlaps ring) --------
        if (MODE2) {
            float* Ce = C_ + (size_t)(e * 1024 + mt * 128) * 2048 + nt * 128;
            #pragma unroll
            for (int st = 0; st < 2; st++)
                #pragma unroll
                for (int j = 0; j < 4; j++) {
                    const int r0 = wm * 32 + st * 16 + (lane >> 2);
                    const int cc = wn * 32 + j * 8 + (lane & 3) * 2;
                    float2 v0; v0.x = acc[st][j][0]; v0.y = acc[st][j][1];
                    float2 v1; v1.x = acc[st][j][2]; v1.y = acc[st][j][3];
                    *reinterpret_cast<float2*>(Ce + (size_t)r0 * 2048 + cc) = v0;
                    *reinterpret_cast<float2*>(Ce + (size_t)(r0 + 8) * 2048 + cc) = v1;
                }
        } else {
            // gate = acc[st][j] (local cols 0..15), up = acc[st][j+2]
            // (local cols 16..31), same output pair. Register SwiGLU.
            __half* scrb = g_scr + (size_t)(e * 1024 + mt * 128) * 4096
                         + (size_t)nt * 64 + wn * 16;
            #pragma unroll
            for (int st = 0; st < 2; st++)
                #pragma unroll
                for (int j = 0; j < 2; j++) {
                    const int r0 = wm * 32 + st * 16 + (lane >> 2);
                    const int cc = j * 8 + (lane & 3) * 2;
                    const float i0 = silu_mul(acc[st][j][0], acc[st][j + 2][0]);
                    const float i1 = silu_mul(acc[st][j][1], acc[st][j + 2][1]);
                    const float i2 = silu_mul(acc[st][j][2], acc[st][j + 2][2]);
                    const float i3 = silu_mul(acc[st][j][3], acc[st][j + 2][3]);
                    *reinterpret_cast<uint32_t*>(scrb + (size_t)r0 * 4096 + cc) = pkh(i0, i1);
                    *reinterpret_cast<uint32_t*>(scrb + (size_t)(r0 + 8) * 4096 + cc) = pkh(i2, i3);
                }
        }
    }
}

// ============================================================================
extern "C" void kernel_launch(void* const* d_in, const int* in_sizes, int n_in,
                              void* d_out, int out_size) {
    const float* X   = (const float*)d_in[0];   // (8192, 2048)
    const float* Wgu = (const float*)d_in[1];   // (8, 2048, 8192)
    const float* Wd  = (const float*)d_in[2];   // (8, 4096, 2048)
    float* out = (float*)d_out;                 // (8192, 2048)

    cudaFuncSetAttribute(gemm_ker<2048, 64, false>,
                         cudaFuncAttributeMaxDynamicSharedMemorySize, SMEM_BYTES);
    cudaFuncSetAttribute(gemm_ker<4096, 16, true>,
                         cudaFuncAttributeMaxDynamicSharedMemorySize, SMEM_BYTES);

    gemm_ker<2048, 64, false><<<NSM, 640, SMEM_BYTES>>>(X, Wgu, nullptr);
    gemm_ker<4096, 16, true><<<NSM, 640, SMEM_BYTES>>>(nullptr, Wd, out);
}